// round 5
// baseline (speedup 1.0000x reference)
#include <cuda_runtime.h>
#include <cuda_bf16.h>
#include <cstdint>

#define BATCH 2048
#define NCLS  1000
#define FDIM  128
#define TM    64
#define TN    64

__device__ __forceinline__ uint32_t smem_u32(const void* p) {
    uint32_t a;
    asm("{ .reg .u64 t; cvta.to.shared.u64 t, %1; cvt.u32.u64 %0, t; }" : "=r"(a) : "l"(p));
    return a;
}

__device__ __forceinline__ uint32_t pack_bf16(float x, float y) {
    __nv_bfloat162 p = __float22bfloat162_rn(make_float2(x, y));
    return *(uint32_t*)&p;
}

#define LDSM_X4(r0, r1, r2, r3, addr) \
    asm volatile("ldmatrix.sync.aligned.m8n8.x4.shared.b16 {%0,%1,%2,%3}, [%4];" \
                 : "=r"(r0), "=r"(r1), "=r"(r2), "=r"(r3) : "r"(addr))

#define MMA_BF16(c, a, b) \
    asm volatile("mma.sync.aligned.m16n8k16.row.col.f32.bf16.bf16.f32 " \
                 "{%0,%1,%2,%3}, {%4,%5,%6,%7}, {%8,%9}, {%0,%1,%2,%3};" \
                 : "+f"((c)[0]), "+f"((c)[1]), "+f"((c)[2]), "+f"((c)[3]) \
                 : "r"((a)[0]), "r"((a)[1]), "r"((a)[2]), "r"((a)[3]), \
                   "r"((b)[0]), "r"((b)[1]))

__global__ void zero_like_kernel(float* like_slot) { *like_slot = 0.0f; }

// Fused: tile fill (f32->bf16 + fp32 norms), HMMA GEMM, fused epilogue.
// 64x64 tile, 128 threads (4 warps, 32x32 warp tiles) -> 512 CTAs for latency hiding.
__global__ __launch_bounds__(128) void lgm_kernel(
    const float* __restrict__ feat,
    const int* __restrict__ label,
    const float* __restrict__ centers,
    float* __restrict__ out)
{
    // swizzled tiles: row stride 256B (128 bf16), 16B chunks, chunk ^= (row&7)
    __shared__ __align__(16) char As[TM * 256];
    __shared__ __align__(16) char Bs[TN * 256];
    __shared__ float s_fn[TM];
    __shared__ float s_cn[TN];

    const int tid  = threadIdx.x;
    const int lane = tid & 31;
    const int wid  = tid >> 5;
    const int rowBase = blockIdx.y * TM;
    const int colBase = blockIdx.x * TN;

    // ---- fill A (feat): 64 rows, 16 chunks/row, 8 rows per iteration ----
    #pragma unroll
    for (int it = 0; it < 8; it++) {
        int row = it * 8 + (tid >> 4);
        int chunk = tid & 15;
        const float4* p = (const float4*)(feat + (size_t)(rowBase + row) * FDIM + chunk * 8);
        float4 v0 = p[0], v1 = p[1];
        float s = v0.x*v0.x + v0.y*v0.y + v0.z*v0.z + v0.w*v0.w
                + v1.x*v1.x + v1.y*v1.y + v1.z*v1.z + v1.w*v1.w;
        #pragma unroll
        for (int o = 8; o; o >>= 1) s += __shfl_xor_sync(0xffffffffu, s, o);
        if (chunk == 0) s_fn[row] = s;
        uint4 w = make_uint4(pack_bf16(v0.x, v0.y), pack_bf16(v0.z, v0.w),
                             pack_bf16(v1.x, v1.y), pack_bf16(v1.z, v1.w));
        *(uint4*)(As + row * 256 + ((chunk ^ (row & 7)) << 4)) = w;
    }
    // ---- fill B (centers), zero-padded past NCLS ----
    #pragma unroll
    for (int it = 0; it < 8; it++) {
        int row = it * 8 + (tid >> 4);
        int chunk = tid & 15;
        int c = colBase + row;
        float4 v0 = make_float4(0.f,0.f,0.f,0.f), v1 = v0;
        if (c < NCLS) {
            const float4* p = (const float4*)(centers + (size_t)c * FDIM + chunk * 8);
            v0 = p[0]; v1 = p[1];
        }
        float s = v0.x*v0.x + v0.y*v0.y + v0.z*v0.z + v0.w*v0.w
                + v1.x*v1.x + v1.y*v1.y + v1.z*v1.z + v1.w*v1.w;
        #pragma unroll
        for (int o = 8; o; o >>= 1) s += __shfl_xor_sync(0xffffffffu, s, o);
        if (chunk == 0) s_cn[row] = s;
        uint4 w = make_uint4(pack_bf16(v0.x, v0.y), pack_bf16(v0.z, v0.w),
                             pack_bf16(v1.x, v1.y), pack_bf16(v1.z, v1.w));
        *(uint4*)(Bs + row * 256 + ((chunk ^ (row & 7)) << 4)) = w;
    }
    __syncthreads();

    // ---- HMMA mainloop: 2x2 warps, warp tile 32x32 ----
    const int wm = wid & 1;
    const int wn = wid >> 1;
    const uint32_t aBase = smem_u32(As);
    const uint32_t bBase = smem_u32(Bs);

    float acc[2][4][4] = {};   // [mstep][nstep][d]

    #pragma unroll
    for (int ks = 0; ks < 8; ks++) {
        const int kc = ks * 2 + (lane >> 4);
        uint32_t a[2][4];
        #pragma unroll
        for (int ms = 0; ms < 2; ms++) {
            int r = wm * 32 + ms * 16 + (lane & 15);
            uint32_t addr = aBase + r * 256 + ((kc ^ (r & 7)) << 4);
            LDSM_X4(a[ms][0], a[ms][1], a[ms][2], a[ms][3], addr);
        }
        uint32_t b[4][2];
        #pragma unroll
        for (int np = 0; np < 2; np++) {
            int r = wn * 32 + np * 16 + (lane & 15);
            uint32_t addr = bBase + r * 256 + ((kc ^ (r & 7)) << 4);
            uint32_t r0, r1, r2, r3;
            LDSM_X4(r0, r1, r2, r3, addr);
            b[np*2][0] = r0; b[np*2+1][0] = r1;
            b[np*2][1] = r2; b[np*2+1][1] = r3;
        }
        #pragma unroll
        for (int ms = 0; ms < 2; ms++)
            #pragma unroll
            for (int ns = 0; ns < 4; ns++)
                MMA_BF16(acc[ms][ns], a[ms], b[ns]);
    }

    // ---- fused epilogue ----
    float* logits = out;
    float* margin = out + (size_t)BATCH * NCLS;
    float* like   = out + 2ull * BATCH * NCLS;

    const int g  = lane >> 2;    // row within 8-row group
    const int tl = lane & 3;     // col pair

    #pragma unroll
    for (int ms = 0; ms < 2; ms++) {
        #pragma unroll
        for (int half = 0; half < 2; half++) {
            int rloc = wm * 32 + ms * 16 + g + half * 8;
            int r = rowBase + rloc;
            float fn = s_fn[rloc];
            int lb = label[r];
            #pragma unroll
            for (int ns = 0; ns < 4; ns++) {
                int cloc = wn * 32 + ns * 8 + tl * 2;
                int c = colBase + cloc;
                if (c < NCLS) {   // NCLS even -> float2 all-or-nothing
                    float d0 = acc[ms][ns][half * 2];
                    float d1 = acc[ms][ns][half * 2 + 1];
                    float dist0 = fn + s_cn[cloc]     - 2.0f * d0;
                    float dist1 = fn + s_cn[cloc + 1] - 2.0f * d1;
                    float l0 = -0.5f * dist0, l1 = -0.5f * dist1;
                    bool h0 = (c == lb), h1 = (c + 1 == lb);
                    float m0 = h0 ? 2.0f * l0 : l0;
                    float m1 = h1 ? 2.0f * l1 : l1;
                    if (h0) atomicAdd(like, dist0 * (0.5f / (float)BATCH));
                    if (h1) atomicAdd(like, dist1 * (0.5f / (float)BATCH));
                    *(float2*)(logits + (size_t)r * NCLS + c) = make_float2(l0, l1);
                    *(float2*)(margin + (size_t)r * NCLS + c) = make_float2(m0, m1);
                }
            }
        }
    }
}

extern "C" void kernel_launch(void* const* d_in, const int* in_sizes, int n_in,
                              void* d_out, int out_size) {
    const float* feat    = (const float*)d_in[0];
    const int*   label   = (const int*)d_in[1];
    const float* centers = (const float*)d_in[2];
    float*       out     = (float*)d_out;

    zero_like_kernel<<<1, 1>>>(out + 2ull * BATCH * NCLS);

    dim3 grid((NCLS + TN - 1) / TN, BATCH / TM);   // 16 x 32 = 512 CTAs
    lgm_kernel<<<grid, 128>>>(feat, label, centers, out);
}

// round 7
// speedup vs baseline: 1.4673x; 1.4673x over previous
#include <cuda_runtime.h>
#include <cuda_bf16.h>
#include <cstdint>

#define BATCH 2048
#define NCLS  1000
#define NPAD  1024
#define FDIM  128
#define TM    64
#define TN    64

// ---- device scratch ----
__device__ __nv_bfloat16 g_featb[BATCH * FDIM];
__device__ __nv_bfloat16 g_centb[NPAD * FDIM];
__device__ float g_fnorm[BATCH];
__device__ float g_cnorm[NPAD];
__device__ float g_like_part[256];

__device__ __forceinline__ uint32_t smem_u32(const void* p) {
    uint32_t a;
    asm("{ .reg .u64 t; cvta.to.shared.u64 t, %1; cvt.u32.u64 %0, t; }" : "=r"(a) : "l"(p));
    return a;
}
__device__ __forceinline__ uint32_t pack_bf16(float x, float y) {
    __nv_bfloat162 p = __float22bfloat162_rn(make_float2(x, y));
    return *(uint32_t*)&p;
}

#define CP_ASYNC16(dst, src) \
    asm volatile("cp.async.cg.shared.global [%0], [%1], 16;" :: "r"(dst), "l"(src))
#define CP_COMMIT() asm volatile("cp.async.commit_group;" ::: "memory")
#define CP_WAIT0()  asm volatile("cp.async.wait_group 0;" ::: "memory")

#define LDSM_X4(r0, r1, r2, r3, addr) \
    asm volatile("ldmatrix.sync.aligned.m8n8.x4.shared.b16 {%0,%1,%2,%3}, [%4];" \
                 : "=r"(r0), "=r"(r1), "=r"(r2), "=r"(r3) : "r"(addr))

#define MMA_BF16(c, a, b) \
    asm volatile("mma.sync.aligned.m16n8k16.row.col.f32.bf16.bf16.f32 " \
                 "{%0,%1,%2,%3}, {%4,%5,%6,%7}, {%8,%9}, {%0,%1,%2,%3};" \
                 : "+f"((c)[0]), "+f"((c)[1]), "+f"((c)[2]), "+f"((c)[3]) \
                 : "r"((a)[0]), "r"((a)[1]), "r"((a)[2]), "r"((a)[3]), \
                   "r"((b)[0]), "r"((b)[1]))

// ---- prep: bf16 convert + fp32 norms + exact fp32 likelihood partials ----
// 384 blocks x 256 threads (8 warps). Blocks 0..255: feat rows (8/block).
// Blocks 256..383: center rows (8/block), zero-padded past NCLS.
__global__ __launch_bounds__(256) void prep_kernel(
    const float* __restrict__ feat,
    const int* __restrict__ label,
    const float* __restrict__ centers)
{
    __shared__ float s_part[8];
    const int wid  = threadIdx.x >> 5;
    const int lane = threadIdx.x & 31;

    if (blockIdx.x < 256) {
        int row = blockIdx.x * 8 + wid;
        float4 v = ((const float4*)(feat + (size_t)row * FDIM))[lane];
        // bf16 store
        uint2 w = make_uint2(pack_bf16(v.x, v.y), pack_bf16(v.z, v.w));
        ((uint2*)(g_featb + (size_t)row * FDIM))[lane] = w;
        // norm
        float s = v.x*v.x + v.y*v.y + v.z*v.z + v.w*v.w;
        // likelihood term: ||f - c_label||^2 (exact fp32)
        int lb = label[row];
        float4 c = ((const float4*)(centers + (size_t)lb * FDIM))[lane];
        float dx = v.x - c.x, dy = v.y - c.y, dz = v.z - c.z, dw = v.w - c.w;
        float q = dx*dx + dy*dy + dz*dz + dw*dw;
        #pragma unroll
        for (int o = 16; o; o >>= 1) {
            s += __shfl_xor_sync(0xffffffffu, s, o);
            q += __shfl_xor_sync(0xffffffffu, q, o);
        }
        if (lane == 0) { g_fnorm[row] = s; s_part[wid] = q; }
        __syncthreads();
        if (threadIdx.x == 0) {
            float t = 0.f;
            #pragma unroll
            for (int i = 0; i < 8; i++) t += s_part[i];
            g_like_part[blockIdx.x] = t;
        }
    } else {
        int row = (blockIdx.x - 256) * 8 + wid;
        float4 v = make_float4(0.f, 0.f, 0.f, 0.f);
        if (row < NCLS) v = ((const float4*)(centers + (size_t)row * FDIM))[lane];
        uint2 w = make_uint2(pack_bf16(v.x, v.y), pack_bf16(v.z, v.w));
        ((uint2*)(g_centb + (size_t)row * FDIM))[lane] = w;
        float s = v.x*v.x + v.y*v.y + v.z*v.z + v.w*v.w;
        #pragma unroll
        for (int o = 16; o; o >>= 1) s += __shfl_xor_sync(0xffffffffu, s, o);
        if (lane == 0) g_cnorm[row] = s;
    }
}

// ---- main: cp.async bf16 fills + HMMA + fused epilogue (no atomics) ----
__global__ __launch_bounds__(128) void lgm_kernel(
    const int* __restrict__ label,
    float* __restrict__ out)
{
    __shared__ __align__(16) char As[TM * 256];   // 64 rows x 128 bf16 (256B), XOR-swizzled
    __shared__ __align__(16) char Bs[TN * 256];
    __shared__ float s_fn[TM];
    __shared__ float s_cn[TN];

    const int tid  = threadIdx.x;
    const int lane = tid & 31;
    const int wid  = tid >> 5;
    const int rowBase = blockIdx.y * TM;
    const int colBase = blockIdx.x * TN;
    const uint32_t aBase = smem_u32(As);
    const uint32_t bBase = smem_u32(Bs);

    // fills: 1024 16B chunks per tile, 8 per thread per tile
    #pragma unroll
    for (int it = 0; it < 8; it++) {
        int idx = it * 128 + tid;
        int row = idx >> 4, chunk = idx & 15;
        uint32_t doff = row * 256 + ((chunk ^ (row & 7)) << 4);
        CP_ASYNC16(aBase + doff, g_featb + (size_t)(rowBase + row) * FDIM + chunk * 8);
        CP_ASYNC16(bBase + doff, g_centb + (size_t)(colBase + row) * FDIM + chunk * 8);
    }
    CP_COMMIT();

    // stage norms while cp.async is in flight
    if (tid < TM) s_fn[tid] = g_fnorm[rowBase + tid];
    else if (tid < TM + TN - 64) ;   // (TM==TN==64: second half below)
    if (tid >= 64) s_cn[tid - 64] = g_cnorm[colBase + (tid - 64)];

    // likelihood finalization by one warp of block (0,0) — independent of GEMM
    if (blockIdx.x == 0 && blockIdx.y == 0 && wid == 3) {
        float t = 0.f;
        #pragma unroll
        for (int i = 0; i < 8; i++) t += g_like_part[lane + i * 32];
        #pragma unroll
        for (int o = 16; o; o >>= 1) t += __shfl_xor_sync(0xffffffffu, t, o);
        if (lane == 0) out[2ull * BATCH * NCLS] = t * (0.5f / (float)BATCH);
    }

    CP_WAIT0();
    __syncthreads();

    // ---- HMMA mainloop: 2x2 warps, warp tile 32x32 ----
    const int wm = wid & 1;
    const int wn = wid >> 1;
    float acc[2][4][4] = {};

    #pragma unroll
    for (int ks = 0; ks < 8; ks++) {
        const int kc = ks * 2 + (lane >> 4);
        uint32_t a[2][4];
        #pragma unroll
        for (int ms = 0; ms < 2; ms++) {
            int r = wm * 32 + ms * 16 + (lane & 15);
            uint32_t addr = aBase + r * 256 + ((kc ^ (r & 7)) << 4);
            LDSM_X4(a[ms][0], a[ms][1], a[ms][2], a[ms][3], addr);
        }
        uint32_t b[4][2];
        #pragma unroll
        for (int np = 0; np < 2; np++) {
            int r = wn * 32 + np * 16 + (lane & 15);
            uint32_t addr = bBase + r * 256 + ((kc ^ (r & 7)) << 4);
            uint32_t r0, r1, r2, r3;
            LDSM_X4(r0, r1, r2, r3, addr);
            b[np*2][0] = r0; b[np*2+1][0] = r1;
            b[np*2][1] = r2; b[np*2+1][1] = r3;
        }
        #pragma unroll
        for (int ms = 0; ms < 2; ms++)
            #pragma unroll
            for (int ns = 0; ns < 4; ns++)
                MMA_BF16(acc[ms][ns], a[ms], b[ns]);
    }

    // ---- fused epilogue ----
    float* logits = out;
    float* margin = out + (size_t)BATCH * NCLS;
    const int g  = lane >> 2;
    const int tl = lane & 3;

    #pragma unroll
    for (int ms = 0; ms < 2; ms++) {
        #pragma unroll
        for (int half = 0; half < 2; half++) {
            int rloc = wm * 32 + ms * 16 + g + half * 8;
            int r = rowBase + rloc;
            float fn = s_fn[rloc];
            int lb = label[r];
            #pragma unroll
            for (int ns = 0; ns < 4; ns++) {
                int cloc = wn * 32 + ns * 8 + tl * 2;
                int c = colBase + cloc;
                if (c < NCLS) {
                    float d0 = acc[ms][ns][half * 2];
                    float d1 = acc[ms][ns][half * 2 + 1];
                    float dist0 = fn + s_cn[cloc]     - 2.0f * d0;
                    float dist1 = fn + s_cn[cloc + 1] - 2.0f * d1;
                    float l0 = -0.5f * dist0, l1 = -0.5f * dist1;
                    float m0 = (c     == lb) ? 2.0f * l0 : l0;
                    float m1 = (c + 1 == lb) ? 2.0f * l1 : l1;
                    *(float2*)(logits + (size_t)r * NCLS + c) = make_float2(l0, l1);
                    *(float2*)(margin + (size_t)r * NCLS + c) = make_float2(m0, m1);
                }
            }
        }
    }
}

extern "C" void kernel_launch(void* const* d_in, const int* in_sizes, int n_in,
                              void* d_out, int out_size) {
    const float* feat    = (const float*)d_in[0];
    const int*   label   = (const int*)d_in[1];
    const float* centers = (const float*)d_in[2];
    float*       out     = (float*)d_out;

    prep_kernel<<<384, 256>>>(feat, label, centers);

    dim3 grid(NPAD / TN, BATCH / TM);   // 16 x 32 = 512 CTAs
    lgm_kernel<<<grid, 128>>>(label, out);
}